// round 7
// baseline (speedup 1.0000x reference)
#include <cuda_runtime.h>
#include <cuda_bf16.h>
#include <math.h>

// Problem constants
#define BATCH   32
#define C_COMB  448
#define HW_IN   32
#define P_IN    1024
#define HW_FEAT 64
#define N_POS   4096
#define D_PROJ  100
#define OUT_HW  256

// Scratch (device globals; no allocation allowed)
__device__ float g_Wt[C_COMB * D_PROJ];          // [448,100]  W^T
__device__ float g_meanT[N_POS * D_PROJ];        // [4096,100] mean^T
__device__ float g_P[BATCH * P_IN * D_PROJ];     // [32,1024,100]
__device__ float g_dist[BATCH * N_POS];          // [32,4096]

// ---------------------------------------------------------------------------
// Packed fp32x2 helpers (sm_103a FFMA2 — PTX only)
__device__ __forceinline__ void ffma2(unsigned long long& acc,
                                      unsigned long long a, unsigned long long b) {
    asm("fma.rn.f32x2 %0, %1, %2, %0;" : "+l"(acc) : "l"(a), "l"(b));
}
__device__ __forceinline__ unsigned long long pack2(float x, float y) {
    unsigned long long r;
    asm("mov.b64 %0, {%1,%2};" : "=l"(r) : "f"(x), "f"(y));
    return r;
}
__device__ __forceinline__ void unpack2(unsigned long long v, float& lo, float& hi) {
    asm("mov.b64 {%0,%1}, %2;" : "=f"(lo), "=f"(hi) : "l"(v));
}

// ---------------------------------------------------------------------------
__global__ void transpose_w_kernel(const float* __restrict__ proj_w) {
    int i = blockIdx.x * 256 + threadIdx.x;
    if (i < C_COMB * D_PROJ) {
        int c = i / D_PROJ, d = i % D_PROJ;
        g_Wt[i] = proj_w[d * C_COMB + c];
    }
}

__global__ void transpose_mean_kernel(const float* __restrict__ mean) {
    int i = blockIdx.x * 256 + threadIdx.x;
    if (i < N_POS * D_PROJ) {
        int n = i / D_PROJ, d = i % D_PROJ;
        g_meanT[i] = mean[d * N_POS + n];
    }
}

// ---------------------------------------------------------------------------
// Kernel 1: projection GEMM at 32x32 (interp/proj commute).
// P[b,p,d] = sum_c combined[b,c,p] * Wt[c,d] + proj_b[d]
// Block: 128 p x 104 d(padded), K=448. 208 active threads, 8p x 8d tiles, FFMA2.
#define WS_PITCH 104

__global__ void __launch_bounds__(256, 2) proj_kernel(
    const float* __restrict__ combined,
    const float* __restrict__ proj_b)
{
    const int b  = blockIdx.y;
    const int p0 = blockIdx.x * 128;
    const int tid = threadIdx.x;

    __shared__ float Xs[16][128];
    __shared__ float Ws[16][WS_PITCH];

    const int pg = tid / 13;     // 0..15 (for tid<208)
    const int dg = tid % 13;     // 0..12

    unsigned long long acc[8][4];
#pragma unroll
    for (int i = 0; i < 8; i++)
#pragma unroll
        for (int j = 0; j < 4; j++) acc[i][j] = 0ULL;

    const float* Xg = combined + (size_t)b * C_COMB * P_IN + p0;

    for (int c0 = 0; c0 < C_COMB; c0 += 16) {
#pragma unroll
        for (int i = tid; i < 16 * 128; i += 256) {
            int kk = i >> 7, pp = i & 127;
            Xs[kk][pp] = Xg[(size_t)(c0 + kk) * P_IN + pp];
        }
        for (int i = tid; i < 16 * WS_PITCH; i += 256) {
            int kk = i / WS_PITCH, dd = i - kk * WS_PITCH;
            Ws[kk][dd] = (dd < D_PROJ) ? g_Wt[(c0 + kk) * D_PROJ + dd] : 0.f;
        }
        __syncthreads();

        if (tid < 208) {
#pragma unroll
            for (int k = 0; k < 16; k++) {
                float4 A0 = *(const float4*)&Xs[k][pg * 8];
                float4 A1 = *(const float4*)&Xs[k][pg * 8 + 4];
                ulonglong2 W0 = *(const ulonglong2*)&Ws[k][dg * 8];
                ulonglong2 W1 = *(const ulonglong2*)&Ws[k][dg * 8 + 4];
                float av[8] = {A0.x, A0.y, A0.z, A0.w, A1.x, A1.y, A1.z, A1.w};
#pragma unroll
                for (int j = 0; j < 8; j++) {
                    unsigned long long ab = pack2(av[j], av[j]);
                    ffma2(acc[j][0], ab, W0.x);
                    ffma2(acc[j][1], ab, W0.y);
                    ffma2(acc[j][2], ab, W1.x);
                    ffma2(acc[j][3], ab, W1.y);
                }
            }
        }
        __syncthreads();
    }

    if (tid < 208) {
#pragma unroll
        for (int j = 0; j < 8; j++) {
            int p = p0 + pg * 8 + j;
            float* O = g_P + (size_t)b * (P_IN * D_PROJ) + (size_t)p * D_PROJ;
#pragma unroll
            for (int q = 0; q < 4; q++) {
                int d = dg * 8 + 2 * q;
                float lo, hi;
                unpack2(acc[j][q], lo, hi);
                if (d < D_PROJ)     O[d]     = lo + proj_b[d];
                if (d + 1 < D_PROJ) O[d + 1] = hi + proj_b[d + 1];
            }
        }
    }
}

// ---------------------------------------------------------------------------
// Kernel 2: per-position Mahalanobis. One block per n.
// GEMM: 8b x 8d register tiles with FFMA2, c-loop split in two (104 threads).
#define SG_PITCH 104
#define DT_PITCH 32
#define N_DG     13
// floats: Sigma 100*104 + dT 104*32 + part 32*13
#define MAHA_SMEM ((100 * SG_PITCH + 104 * DT_PITCH + 32 * N_DG) * 4)

__global__ void __launch_bounds__(128, 4) maha_kernel(
    const float* __restrict__ inv_cov)
{
    extern __shared__ float smem[];
    float* Sg   = smem;                          // [100][104] (cols 100..103 zero)
    float* dT   = Sg + 100 * SG_PITCH;           // [104][32]  diffT[d][b]
    float* part = dT + 104 * DT_PITCH;           // [32][13]

    const int n   = blockIdx.x;
    const int tid = threadIdx.x;

    // ---- load Sigma_n (40KB DRAM), pad to pitch 104 ----
    const float* Sgl = inv_cov + (size_t)n * (D_PROJ * D_PROJ);
#pragma unroll 4
    for (int i = tid; i < 100 * SG_PITCH; i += 128) {
        int c = i / SG_PITCH, d = i - c * SG_PITCH;
        Sg[i] = (d < D_PROJ) ? Sgl[c * D_PROJ + d] : 0.f;
    }
    // zero dT pad rows (d = 100..103) and partials
    if (tid < 128) {
        dT[100 * DT_PITCH + tid] = 0.f;
    }
    for (int i = tid; i < 32 * N_DG; i += 128) part[i] = 0.f;

    // ---- bilinear corner setup (half-pixel, 32->64) ----
    const int Y = n >> 6, X = n & 63;
    float sy = 0.5f * (float)Y - 0.25f;
    float sx = 0.5f * (float)X - 0.25f;
    float fy = floorf(sy), fx = floorf(sx);
    int y0 = max(0, (int)fy), y1 = min(HW_IN - 1, (int)fy + 1);
    int x0 = max(0, (int)fx), x1 = min(HW_IN - 1, (int)fx + 1);
    float wy1 = sy - fy, wy0 = 1.f - wy1;
    float wx1 = sx - fx, wx0 = 1.f - wx1;
    float w00 = wy0 * wx0, w01 = wy0 * wx1, w10 = wy1 * wx0, w11 = wy1 * wx1;
    int p00 = (y0 * HW_IN + x0) * D_PROJ, p01 = (y0 * HW_IN + x1) * D_PROJ;
    int p10 = (y1 * HW_IN + x0) * D_PROJ, p11 = (y1 * HW_IN + x1) * D_PROJ;

    // ---- diff (L2 gathers; g_P 13MB resident). b fastest -> conflict-free STS ----
    const float* mT = g_meanT + (size_t)n * D_PROJ;
#pragma unroll 2
    for (int i = tid; i < BATCH * D_PROJ; i += 128) {
        int d = i >> 5, b = i & 31;
        const float* Pb = g_P + (size_t)b * (P_IN * D_PROJ) + d;
        float v = w00 * Pb[p00] + w01 * Pb[p01] + w10 * Pb[p10] + w11 * Pb[p11];
        dT[d * DT_PITCH + b] = v - mT[d];
    }
    __syncthreads();

    // ---- GEMM + quadratic form: 104 threads, 8b x 8d tiles, FFMA2 ----
    if (tid < 104) {
        const int ci = (tid >= 52) ? 1 : 0;
        const int r  = tid - ci * 52;
        const int di = r >> 2;           // 0..12
        const int bi = r & 3;            // 0..3
        const int b0 = bi * 8, d0 = di * 8;
        const int cbeg = ci * 50, cend = cbeg + 50;

        unsigned long long acc[8][4];
#pragma unroll
        for (int j = 0; j < 8; j++)
#pragma unroll
            for (int q = 0; q < 4; q++) acc[j][q] = 0ULL;

#pragma unroll 2
        for (int c = cbeg; c < cend; c++) {
            const float* aP = &dT[c * DT_PITCH + b0];
            float4 A0 = *(const float4*)aP;
            float4 A1 = *(const float4*)(aP + 4);
            const float* wP = &Sg[c * SG_PITCH + d0];
            ulonglong2 W0 = *(const ulonglong2*)wP;
            ulonglong2 W1 = *(const ulonglong2*)(wP + 4);
            float av[8] = {A0.x, A0.y, A0.z, A0.w, A1.x, A1.y, A1.z, A1.w};
#pragma unroll
            for (int j = 0; j < 8; j++) {
                unsigned long long ab = pack2(av[j], av[j]);
                ffma2(acc[j][0], ab, W0.x);
                ffma2(acc[j][1], ab, W0.y);
                ffma2(acc[j][2], ab, W1.x);
                ffma2(acc[j][3], ab, W1.y);
            }
        }

        // quadratic-form partials: sum_d T[b,d]*diff[b,d] over this d-tile
#pragma unroll
        for (int j = 0; j < 8; j++) {
            float s = 0.f;
#pragma unroll
            for (int q = 0; q < 4; q++) {
                float lo, hi;
                unpack2(acc[j][q], lo, hi);
                s += lo * dT[(d0 + 2 * q)     * DT_PITCH + b0 + j];
                s += hi * dT[(d0 + 2 * q + 1) * DT_PITCH + b0 + j];
            }
            atomicAdd(&part[(b0 + j) * N_DG + di], s);  // 2-way contention (c-split)
        }
    }
    __syncthreads();

    if (tid < BATCH) {
        float s = 0.f;
#pragma unroll
        for (int k = 0; k < N_DG; k++) s += part[tid * N_DG + k];
        g_dist[(size_t)tid * N_POS + n] = s;
    }
}

// ---------------------------------------------------------------------------
// Kernel 3: normalize + bilinear 64->256 upsample.
__global__ void __launch_bounds__(256) upsample_kernel(
    const float* __restrict__ nmin_p,
    const float* __restrict__ nmax_p,
    float* __restrict__ out)
{
    const int b = blockIdx.y;
    const int i = blockIdx.x * 256 + threadIdx.x;
    const int Y = i >> 8, X = i & 255;

    float sy = 0.25f * (float)Y - 0.375f;
    float sx = 0.25f * (float)X - 0.375f;
    float fy = floorf(sy), fx = floorf(sx);
    int y0 = max(0, (int)fy), y1 = min(HW_FEAT - 1, (int)fy + 1);
    int x0 = max(0, (int)fx), x1 = min(HW_FEAT - 1, (int)fx + 1);
    float wy1 = sy - fy, wy0 = 1.f - wy1;
    float wx1 = sx - fx, wx0 = 1.f - wx1;

    const float* D = g_dist + (size_t)b * N_POS;
    float v = wy0 * (wx0 * D[y0 * HW_FEAT + x0] + wx1 * D[y0 * HW_FEAT + x1])
            + wy1 * (wx0 * D[y1 * HW_FEAT + x0] + wx1 * D[y1 * HW_FEAT + x1]);

    float nmin = *nmin_p, nmax = *nmax_p;
    out[(size_t)b * (OUT_HW * OUT_HW) + i] = (v - nmin) / (nmax - nmin + 1e-8f);
}

// ---------------------------------------------------------------------------
extern "C" void kernel_launch(void* const* d_in, const int* in_sizes, int n_in,
                              void* d_out, int out_size)
{
    const float* combined = (const float*)d_in[0];
    const float* proj_w   = (const float*)d_in[1];
    const float* proj_b   = (const float*)d_in[2];
    const float* mean     = (const float*)d_in[3];
    const float* inv_cov  = (const float*)d_in[4];
    const float* nmin     = (const float*)d_in[5];
    const float* nmax     = (const float*)d_in[6];
    float* out            = (float*)d_out;

    cudaFuncSetAttribute(maha_kernel,
                         cudaFuncAttributeMaxDynamicSharedMemorySize, MAHA_SMEM);

    transpose_w_kernel<<<(C_COMB * D_PROJ + 255) / 256, 256>>>(proj_w);
    transpose_mean_kernel<<<(N_POS * D_PROJ + 255) / 256, 256>>>(mean);
    proj_kernel<<<dim3(8, BATCH), 256>>>(combined, proj_b);
    maha_kernel<<<N_POS, 128, MAHA_SMEM>>>(inv_cov);
    upsample_kernel<<<dim3(OUT_HW * OUT_HW / 256, BATCH), 256>>>(nmin, nmax, out);
}

// round 9
// speedup vs baseline: 1.5241x; 1.5241x over previous
#include <cuda_runtime.h>
#include <cuda_bf16.h>
#include <math.h>

// Problem constants
#define BATCH   32
#define C_COMB  448
#define HW_IN   32
#define P_IN    1024
#define HW_FEAT 64
#define N_POS   4096
#define D_PROJ  100
#define OUT_HW  256

// Scratch (device globals; no allocation allowed)
__device__ float g_Wt[C_COMB * D_PROJ];          // [448,100]  W^T
__device__ float g_meanT[N_POS * D_PROJ];        // [4096,100] mean^T
__device__ float g_P[BATCH * P_IN * D_PROJ];     // [32,1024,100]  (p-major, d contiguous)
__device__ float g_dist[BATCH * N_POS];          // [32,4096]

// ---------------------------------------------------------------------------
// Packed fp32x2 helpers (sm_103a FFMA2 — PTX only)
__device__ __forceinline__ void ffma2(unsigned long long& acc,
                                      unsigned long long a, unsigned long long b) {
    asm("fma.rn.f32x2 %0, %1, %2, %0;" : "+l"(acc) : "l"(a), "l"(b));
}
__device__ __forceinline__ unsigned long long pack2(float x, float y) {
    unsigned long long r;
    asm("mov.b64 %0, {%1,%2};" : "=l"(r) : "f"(x), "f"(y));
    return r;
}
__device__ __forceinline__ void unpack2(unsigned long long v, float& lo, float& hi) {
    asm("mov.b64 {%0,%1}, %2;" : "=f"(lo), "=f"(hi) : "l"(v));
}

// ---------------------------------------------------------------------------
__global__ void transpose_w_kernel(const float* __restrict__ proj_w) {
    int i = blockIdx.x * 256 + threadIdx.x;
    if (i < C_COMB * D_PROJ) {
        int c = i / D_PROJ, d = i % D_PROJ;
        g_Wt[i] = proj_w[d * C_COMB + c];
    }
}

__global__ void transpose_mean_kernel(const float* __restrict__ mean) {
    int i = blockIdx.x * 256 + threadIdx.x;
    if (i < N_POS * D_PROJ) {
        int n = i / D_PROJ, d = i % D_PROJ;
        g_meanT[i] = mean[d * N_POS + n];
    }
}

// ---------------------------------------------------------------------------
// Kernel 1: projection GEMM at 32x32 (interp/proj commute).
// P[b,p,d] = sum_c combined[b,c,p] * Wt[c,d] + proj_b[d]
// Warp-broadcast layout: lane = position (32 p per warp-group), each warp owns
// a 28-wide d range; W row values broadcast via LDS.128; FFMA2 accumulators.
// Block = 256 threads: warps 0-3 -> p 0-31 (d ranges 0/28/56/84),
//                      warps 4-7 -> p 32-63.
#define PJ_WPITCH 112

__global__ void __launch_bounds__(256) proj_kernel(
    const float* __restrict__ combined,
    const float* __restrict__ proj_b)
{
    const int b   = blockIdx.y;
    const int p0  = blockIdx.x * 64;
    const int tid = threadIdx.x;
    const int w    = tid >> 5;
    const int lane = tid & 31;
    const int pg   = w >> 2;            // 0/1: which 32-p half
    const int dw   = w & 3;             // d-range index
    const int d0   = dw * 28;

    __shared__ float Xs[32][64];        // [c-chunk][p]
    __shared__ float Ws[32][PJ_WPITCH]; // [c-chunk][d padded]

    // init accumulators with bias (linear: (b + sum) == (sum + b) up to rounding)
    unsigned long long acc[14];
#pragma unroll
    for (int j = 0; j < 14; j++) {
        int d = d0 + 2 * j;
        float lo = (d     < D_PROJ) ? proj_b[d]     : 0.f;
        float hi = (d + 1 < D_PROJ) ? proj_b[d + 1] : 0.f;
        acc[j] = pack2(lo, hi);
    }

    const float* Xg = combined + (size_t)b * C_COMB * P_IN + p0;

    for (int c0 = 0; c0 < C_COMB; c0 += 32) {
        // stage X chunk: 32 c-rows x 64 p (coalesced)
#pragma unroll
        for (int i = tid; i < 32 * 64; i += 256) {
            int kk = i >> 6, pp = i & 63;
            Xs[kk][pp] = Xg[(size_t)(c0 + kk) * P_IN + pp];
        }
        // stage W chunk: 32 c-rows x 112 d (pad zero)
#pragma unroll
        for (int i = tid; i < 32 * PJ_WPITCH; i += 256) {
            int kk = i / PJ_WPITCH, dd = i - kk * PJ_WPITCH;
            Ws[kk][dd] = (dd < D_PROJ) ? g_Wt[(c0 + kk) * D_PROJ + dd] : 0.f;
        }
        __syncthreads();

#pragma unroll 8
        for (int k = 0; k < 32; k++) {
            float a = Xs[k][pg * 32 + lane];              // conflict-free
            unsigned long long ab = pack2(a, a);
            const ulonglong2* Wp = (const ulonglong2*)&Ws[k][d0];  // broadcast
#pragma unroll
            for (int q = 0; q < 7; q++) {
                ulonglong2 Wv = Wp[q];
                ffma2(acc[2 * q],     ab, Wv.x);
                ffma2(acc[2 * q + 1], ab, Wv.y);
            }
        }
        __syncthreads();
    }

    // writeback: lane owns p = p0 + pg*32 + lane, d range [d0, d0+27] (clipped 100)
    {
        int p = p0 + pg * 32 + lane;
        float* O = g_P + (size_t)b * (P_IN * D_PROJ) + (size_t)p * D_PROJ + d0;
        const int nq = (dw == 3) ? 4 : 7;   // d0=84 -> 16 floats covers 84..99
#pragma unroll
        for (int q = 0; q < 7; q++) {
            if (q < nq) {
                float4 v;
                unpack2(acc[2 * q],     v.x, v.y);
                unpack2(acc[2 * q + 1], v.z, v.w);
                *(float4*)(O + 4 * q) = v;
            }
        }
    }
}

// ---------------------------------------------------------------------------
// Kernel 2: per-position Mahalanobis. One block (256 thr) per n.
// lane = batch. Warp w: d-range (w&3)*28, c-range (w>>2)*50 (c-split is linear
// so per-warp partial quadratic sums are exact up to fp reordering).
// smem: Sg[100][112] + dB[32][105] + part[8][32]
#define SG_PITCH 112
#define DB_PITCH 105
#define MAHA_SMEM ((100 * SG_PITCH + BATCH * DB_PITCH + 8 * 32) * 4)

__global__ void __launch_bounds__(256) maha_kernel(
    const float* __restrict__ inv_cov)
{
    extern __shared__ float smem[];
    float* Sg   = smem;                         // [100][112], cols 100..111 zero
    float* dB   = Sg + 100 * SG_PITCH;          // [32][105]  diff[b][d]
    float* part = dB + BATCH * DB_PITCH;        // [8][32]

    const int n    = blockIdx.x;
    const int tid  = threadIdx.x;
    const int w    = tid >> 5;
    const int lane = tid & 31;                  // = batch index
    const int d0   = (w & 3) * 28;
    const int cbeg = (w >> 2) * 50;

    // ---- stage Sigma_n (40KB DRAM), pitch 112, zero-pad ----
    const float* Sgl = inv_cov + (size_t)n * (D_PROJ * D_PROJ);
#pragma unroll 4
    for (int i = tid; i < 100 * SG_PITCH; i += 256) {
        int c = i / SG_PITCH, d = i - c * SG_PITCH;
        Sg[i] = (d < D_PROJ) ? Sgl[c * D_PROJ + d] : 0.f;
    }

    // ---- bilinear corner setup (half-pixel, 32->64) ----
    const int Y = n >> 6, X = n & 63;
    float sy = 0.5f * (float)Y - 0.25f;
    float sx = 0.5f * (float)X - 0.25f;
    float fy = floorf(sy), fx = floorf(sx);
    int y0 = max(0, (int)fy), y1 = min(HW_IN - 1, (int)fy + 1);
    int x0 = max(0, (int)fx), x1 = min(HW_IN - 1, (int)fx + 1);
    float wy1 = sy - fy, wy0 = 1.f - wy1;
    float wx1 = sx - fx, wx0 = 1.f - wx1;
    float w00 = wy0 * wx0, w01 = wy0 * wx1, w10 = wy1 * wx0, w11 = wy1 * wx1;
    int p00 = (y0 * HW_IN + x0) * D_PROJ, p01 = (y0 * HW_IN + x1) * D_PROJ;
    int p10 = (y1 * HW_IN + x0) * D_PROJ, p11 = (y1 * HW_IN + x1) * D_PROJ;

    // ---- diff: gather 4 corners from g_P (L2 resident), coalesced over d ----
    const float* mT = g_meanT + (size_t)n * D_PROJ;
#pragma unroll 2
    for (int i = tid; i < BATCH * D_PROJ; i += 256) {
        int b = i / D_PROJ, d = i - b * D_PROJ;
        const float* Pb = g_P + (size_t)b * (P_IN * D_PROJ) + d;
        float v = w00 * Pb[p00] + w01 * Pb[p01] + w10 * Pb[p10] + w11 * Pb[p11];
        dB[b * DB_PITCH + d] = v - mT[d];      // pitch 105 -> bank 9b+d: distinct
    }
    __syncthreads();

    // ---- GEMM: T[b, d0..d0+27] partial over c in [cbeg, cbeg+50) ----
    unsigned long long acc[14];
#pragma unroll
    for (int j = 0; j < 14; j++) acc[j] = 0ULL;

#pragma unroll 5
    for (int c = cbeg; c < cbeg + 50; c++) {
        float a = dB[lane * DB_PITCH + c];               // conflict-free scalar
        unsigned long long ab = pack2(a, a);
        const ulonglong2* Sp = (const ulonglong2*)&Sg[c * SG_PITCH + d0]; // bcast
#pragma unroll
        for (int q = 0; q < 7; q++) {
            ulonglong2 Sv = Sp[q];
            ffma2(acc[2 * q],     ab, Sv.x);
            ffma2(acc[2 * q + 1], ab, Sv.y);
        }
    }

    // ---- quadratic partial: sum over this warp's d-range ----
    {
        float s = 0.f;
#pragma unroll
        for (int j = 0; j < 14; j++) {
            float lo, hi;
            unpack2(acc[j], lo, hi);
            int d = d0 + 2 * j;
            if (d     < D_PROJ) s += lo * dB[lane * DB_PITCH + d];
            if (d + 1 < D_PROJ) s += hi * dB[lane * DB_PITCH + d + 1];
        }
        part[w * 32 + lane] = s;
    }
    __syncthreads();

    if (tid < BATCH) {
        float s = 0.f;
#pragma unroll
        for (int k = 0; k < 8; k++) s += part[k * 32 + tid];
        g_dist[(size_t)tid * N_POS + n] = s;
    }
}

// ---------------------------------------------------------------------------
// Kernel 3: normalize + bilinear 64->256 upsample (both linear, commute).
__global__ void __launch_bounds__(256) upsample_kernel(
    const float* __restrict__ nmin_p,
    const float* __restrict__ nmax_p,
    float* __restrict__ out)
{
    const int b = blockIdx.y;
    const int i = blockIdx.x * 256 + threadIdx.x;
    const int Y = i >> 8, X = i & 255;

    float sy = 0.25f * (float)Y - 0.375f;
    float sx = 0.25f * (float)X - 0.375f;
    float fy = floorf(sy), fx = floorf(sx);
    int y0 = max(0, (int)fy), y1 = min(HW_FEAT - 1, (int)fy + 1);
    int x0 = max(0, (int)fx), x1 = min(HW_FEAT - 1, (int)fx + 1);
    float wy1 = sy - fy, wy0 = 1.f - wy1;
    float wx1 = sx - fx, wx0 = 1.f - wx1;

    const float* D = g_dist + (size_t)b * N_POS;
    float v = wy0 * (wx0 * D[y0 * HW_FEAT + x0] + wx1 * D[y0 * HW_FEAT + x1])
            + wy1 * (wx0 * D[y1 * HW_FEAT + x0] + wx1 * D[y1 * HW_FEAT + x1]);

    float nmin = *nmin_p, nmax = *nmax_p;
    out[(size_t)b * (OUT_HW * OUT_HW) + i] = (v - nmin) / (nmax - nmin + 1e-8f);
}

// ---------------------------------------------------------------------------
extern "C" void kernel_launch(void* const* d_in, const int* in_sizes, int n_in,
                              void* d_out, int out_size)
{
    const float* combined = (const float*)d_in[0];
    const float* proj_w   = (const float*)d_in[1];
    const float* proj_b   = (const float*)d_in[2];
    const float* mean     = (const float*)d_in[3];
    const float* inv_cov  = (const float*)d_in[4];
    const float* nmin     = (const float*)d_in[5];
    const float* nmax     = (const float*)d_in[6];
    float* out            = (float*)d_out;

    cudaFuncSetAttribute(maha_kernel,
                         cudaFuncAttributeMaxDynamicSharedMemorySize, MAHA_SMEM);

    transpose_w_kernel<<<(C_COMB * D_PROJ + 255) / 256, 256>>>(proj_w);
    transpose_mean_kernel<<<(N_POS * D_PROJ + 255) / 256, 256>>>(mean);
    proj_kernel<<<dim3(P_IN / 64, BATCH), 256>>>(combined, proj_b);
    maha_kernel<<<N_POS, 256, MAHA_SMEM>>>(inv_cov);
    upsample_kernel<<<dim3(OUT_HW * OUT_HW / 256, BATCH), 256>>>(nmin, nmax, out);
}